// round 13
// baseline (speedup 1.0000x reference)
#include <cuda_runtime.h>
#include <cuda_fp16.h>
#include <cstdint>

// ---------------------------------------------------------------------------
// S = q @ k^T  [8192,8192];  G = gelu_exact(S/||S||_row*sqrt(8192));
// out = G @ v  [8192,1024].
// fp16 m16n8k16 mma.sync, fp32 accum (~304 TF/s legacy-path ceiling).
// GEMM1 writes S directly as fp16 in P2 layout (half2 epilogue stores);
// norm+gelu runs IN PLACE on fp16 (no fp32 S buffer at all).
// P2 k-permutation (16-group: slots 4t..4t+3 = logical {2t,2t+1,2t+8,2t+9});
// SLDH=72, 4-stage cp.async ring. GEMM1 fuses row-sumsq; GEMM2 split-K x4.
// ---------------------------------------------------------------------------

static __device__ __half g_Gh [8192ull * 8192ull];    // 128 MB S/G fp16 (P2 cols)
static __device__ __half g_VTh[1024ull * 8192ull];    // 16 MB  v^T fp16 (P2 k)
static __device__ __half g_QTh[8192ull * 1024ull];    // 16 MB  q fp16 (P2 k)
static __device__ __half g_KTh[8192ull * 1024ull];    // 16 MB  k fp16 (P2 k)
static __device__ float  g_P  [4ull * 8192ull * 1024ull]; // 128 MB split-K partials
static __device__ float  g_SQ [8192ull * 128ull];     // 4 MB sumsq partials

__device__ __forceinline__ void cp16(uint32_t dst_s, const void* src) {
    asm volatile("cp.async.cg.shared.global [%0], [%1], 16;\n" :: "r"(dst_s), "l"(src));
}

__device__ __forceinline__ uint2 lds64(uint32_t addr) {
    uint2 r;
    asm volatile("ld.shared.v2.b32 {%0, %1}, [%2];" : "=r"(r.x), "=r"(r.y) : "r"(addr));
    return r;
}

// =========================== unified fp16 GEMM =============================
constexpr int BM = 256, BN = 128;
constexpr int BKH  = 64;                 // halves per k-iter (128B rows + 16B pad)
constexpr int SLDH = 72;                 // halves; pair-stride 36 ≡ 4 mod 16: conflict-free
constexpr int STAGES = 4;
constexpr int TILEAH = BM * SLDH;        // 18432 halves
constexpr int TILEBH = BN * SLDH;        // 9216 halves
constexpr int STAGEH = TILEAH + TILEBH;  // 27648 halves
constexpr unsigned SMEMH_BYTES = STAGES * STAGEH * 2;  // 221184 B
constexpr int ROWB = 32 * SLDH * 2;      // 4608
constexpr int MTB  = 16 * SLDH * 2;      // 2304
constexpr int NTB  = 8 * SLDH * 2;       // 1152

__device__ __forceinline__ void mma_f16(float* d, uint2 a, uint2 a8, uint2 b) {
    asm volatile(
        "mma.sync.aligned.m16n8k16.row.col.f32.f16.f16.f32 "
        "{%0,%1,%2,%3}, {%4,%5,%6,%7}, {%8,%9}, {%0,%1,%2,%3};\n"
        : "+f"(d[0]), "+f"(d[1]), "+f"(d[2]), "+f"(d[3])
        : "r"(a.x), "r"(a8.x), "r"(a.y), "r"(a8.y), "r"(b.x), "r"(b.y));
}

struct FragH {
    uint2 a[4];
    uint2 a8[4];
    uint2 b[8];
};

// G1PHASE: epilogue stores fp16 (P2 cols) + fused sumsq. Else fp32 float2.
template <bool G1PHASE>
__global__ __launch_bounds__(256, 1) void gemm_fp16(
    const __half* __restrict__ A, const __half* __restrict__ B, void* __restrict__ Cv,
    float* __restrict__ sqpart,
    int M, int N, int kcount, int strideA, int strideB)
{
    extern __shared__ __half smh[];
    const uint32_t smem_s = (uint32_t)__cvta_generic_to_shared(smh);

    const int tid  = threadIdx.x;
    const int lane = tid & 31;
    const int wid  = tid >> 5;
    const int wm   = wid & 3;
    const int wn   = wid >> 2;
    const long bm = (long)blockIdx.y * BM;
    const long bn = (long)blockIdx.x * BN;
    const int kbase = blockIdx.z * kcount;

    float acc[4][8][4];
#pragma unroll
    for (int i = 0; i < 4; i++)
#pragma unroll
        for (int j = 0; j < 8; j++)
#pragma unroll
            for (int c = 0; c < 4; c++) acc[i][j][c] = 0.f;

    const int nk = kcount / BKH;

    // ---- staging ----
    const int rowA = tid >> 3;
    const int colh = (tid & 7) * 8;
    const __half* aG = A + (size_t)(bm + rowA) * strideA + kbase + colh;
    const __half* bG = B + (size_t)(bn + rowA) * strideB + kbase + colh;
    const uint32_t dA0 = (uint32_t)(rowA * SLDH + colh) * 2u;
    const uint32_t dB0 = (uint32_t)(TILEAH * 2) + dA0;

    auto load_stage = [&](int s, int kt) {
        const uint32_t sb = smem_s + (uint32_t)s * (STAGEH * 2);
        const __half* ak = aG + kt * BKH;
        const __half* bk = bG + kt * BKH;
#pragma unroll
        for (int i = 0; i < 8; i++)
            cp16(sb + dA0 + i * ROWB, ak + (size_t)i * 32 * strideA);
#pragma unroll
        for (int i = 0; i < 4; i++)
            cp16(sb + dB0 + i * ROWB, bk + (size_t)i * 32 * strideB);
        asm volatile("cp.async.commit_group;\n");
    };

#pragma unroll
    for (int s = 0; s < STAGES - 1; s++) load_stage(s, s);

    // ---- fragment base offsets ----
    const int t    = lane & 3;
    const int qrow = lane >> 2;
    const uint32_t aW0 = (uint32_t)((wm * 64 + qrow) * SLDH + 4 * t) * 2u;
    const uint32_t bW0 = (uint32_t)(TILEAH * 2) +
                         (uint32_t)((wn * 64 + qrow) * SLDH + 4 * t) * 2u;

    FragH f[2];

    auto load_frags = [&](uint32_t aW, uint32_t bW, FragH& F) {
#pragma unroll
        for (int mt = 0; mt < 4; mt++) {
            F.a[mt]  = lds64(aW + mt * MTB);
            F.a8[mt] = lds64(aW + mt * MTB + NTB);
        }
#pragma unroll
        for (int nt = 0; nt < 8; nt++)
            F.b[nt] = lds64(bW + nt * NTB);
    };

    auto mma_all = [&](const FragH& F) {
#pragma unroll
        for (int nt = 0; nt < 8; nt++)
#pragma unroll
            for (int mt = 0; mt < 4; mt++)
                mma_f16(acc[mt][nt], F.a[mt], F.a8[mt], F.b[nt]);
    };

    int stage = 0;
    for (int kt = 0; kt < nk; kt++) {
        asm volatile("cp.async.wait_group %0;\n" :: "n"(STAGES - 2));
        __syncthreads();

        if (kt + STAGES - 1 < nk) {
            int s = stage + STAGES - 1;
            if (s >= STAGES) s -= STAGES;
            load_stage(s, kt + STAGES - 1);
        } else {
            asm volatile("cp.async.commit_group;\n");
        }

        const uint32_t sb = smem_s + (uint32_t)stage * (STAGEH * 2);
        const uint32_t aW = sb + aW0;
        const uint32_t bW = sb + bW0;

        load_frags(aW, bW, f[0]);
#pragma unroll
        for (int g = 0; g < 4; g++) {              // 4 x 16-k groups per kt
            if (g < 3) load_frags(aW + (g + 1) * 32, bW + (g + 1) * 32, f[(g + 1) & 1]);
            mma_all(f[g & 1]);
        }

        if (++stage == STAGES) stage = 0;
    }

    if (G1PHASE) {
        // fused per-row sumsq partials (from fp32 accs, pre-rounding)
        const int pidx = blockIdx.x * 2 + wn;
#pragma unroll
        for (int mt = 0; mt < 4; mt++) {
            float s0 = 0.f, s1 = 0.f;
#pragma unroll
            for (int nt = 0; nt < 8; nt++) {
                s0 += acc[mt][nt][0] * acc[mt][nt][0] + acc[mt][nt][1] * acc[mt][nt][1];
                s1 += acc[mt][nt][2] * acc[mt][nt][2] + acc[mt][nt][3] * acc[mt][nt][3];
            }
            s0 += __shfl_xor_sync(0xffffffffu, s0, 1);
            s0 += __shfl_xor_sync(0xffffffffu, s0, 2);
            s1 += __shfl_xor_sync(0xffffffffu, s1, 1);
            s1 += __shfl_xor_sync(0xffffffffu, s1, 2);
            if (t == 0) {
                long r = bm + wm * 64 + mt * 16 + qrow;
                sqpart[(size_t)r * 128 + pidx]       = s0;
                sqpart[(size_t)(r + 8) * 128 + pidx] = s1;
            }
        }
        // fp16 epilogue in P2 layout: cols (2t,2t+1) of 8-group h=nt&1 land in
        // ADJACENT P2 slots 4t+2h, 4t+2h+1 -> single half2 store per pair.
        __half* Ch = (__half*)Cv;
#pragma unroll
        for (int mt = 0; mt < 4; mt++) {
            long r0 = bm + wm * 64 + mt * 16 + qrow;
#pragma unroll
            for (int nt = 0; nt < 8; nt++) {
                long c0 = bn + wn * 64 + (nt >> 1) * 16 + 4 * t + 2 * (nt & 1);
                *reinterpret_cast<__half2*>(&Ch[(size_t)r0 * N + c0]) =
                    __floats2half2_rn(acc[mt][nt][0], acc[mt][nt][1]);
                *reinterpret_cast<__half2*>(&Ch[(size_t)(r0 + 8) * N + c0]) =
                    __floats2half2_rn(acc[mt][nt][2], acc[mt][nt][3]);
            }
        }
    } else {
        float* C = (float*)Cv + (size_t)blockIdx.z * M * (size_t)N;
#pragma unroll
        for (int mt = 0; mt < 4; mt++) {
            long r0 = bm + wm * 64 + mt * 16 + qrow;
#pragma unroll
            for (int nt = 0; nt < 8; nt++) {
                long c0 = bn + wn * 64 + nt * 8 + 2 * t;
                *reinterpret_cast<float2*>(&C[(size_t)r0 * N + c0]) =
                    make_float2(acc[mt][nt][0], acc[mt][nt][1]);
                *reinterpret_cast<float2*>(&C[(size_t)(r0 + 8) * N + c0]) =
                    make_float2(acc[mt][nt][2], acc[mt][nt][3]);
            }
        }
    }
}

// ======================= staging / elementwise kernels =====================
__device__ __constant__ int c_invM[16] = {0,1,8,9,2,3,10,11,4,5,12,13,6,7,14,15};

__global__ __launch_bounds__(256) void stage_h_kernel(
    const float4* __restrict__ in, __half* __restrict__ out, int ngroups)
{
    int g = blockIdx.x * 256 + threadIdx.x;
    if (g >= ngroups) return;
    float x[16];
    float4 v0 = in[4 * g], v1 = in[4 * g + 1], v2 = in[4 * g + 2], v3 = in[4 * g + 3];
    x[0]=v0.x; x[1]=v0.y; x[2]=v0.z; x[3]=v0.w;
    x[4]=v1.x; x[5]=v1.y; x[6]=v1.z; x[7]=v1.w;
    x[8]=v2.x; x[9]=v2.y; x[10]=v2.z; x[11]=v2.w;
    x[12]=v3.x; x[13]=v3.y; x[14]=v3.z; x[15]=v3.w;
    uint32_t u[8];
#pragma unroll
    for (int j = 0; j < 8; j++) {
        __half2 h2 = __floats2half2_rn(x[c_invM[2 * j]], x[c_invM[2 * j + 1]]);
        u[j] = *reinterpret_cast<uint32_t*>(&h2);
    }
    uint4* dst = reinterpret_cast<uint4*>(out + (size_t)g * 16);
    dst[0] = make_uint4(u[0], u[1], u[2], u[3]);
    dst[1] = make_uint4(u[4], u[5], u[6], u[7]);
}

// IN-PLACE fp16 norm+gelu: scale from sumsq partials, exact erf GELU.
// (P2 layout passes through: gelu is elementwise, norm is perm-invariant.)
__global__ __launch_bounds__(256) void norm_gelu_inplace_kernel(
    __half* __restrict__ Sh, const float* __restrict__ sqpart, int N)
{
    const int row = blockIdx.x;
    float ss = (threadIdx.x < 128) ? sqpart[(size_t)row * 128 + threadIdx.x] : 0.f;
    __shared__ float red[8];
#pragma unroll
    for (int o = 16; o > 0; o >>= 1) ss += __shfl_xor_sync(0xffffffffu, ss, o);
    if ((threadIdx.x & 31) == 0) red[threadIdx.x >> 5] = ss;
    __syncthreads();
    if (threadIdx.x < 32) {
        float v = (threadIdx.x < 8) ? red[threadIdx.x] : 0.f;
#pragma unroll
        for (int o = 4; o > 0; o >>= 1) v += __shfl_xor_sync(0xffffffffu, v, o);
        if (threadIdx.x == 0) red[0] = v;
    }
    __syncthreads();
    const float scale = sqrtf((float)N / red[0]);
    const float inv_sqrt2 = 0.70710678118654752440f;

    uint4* prow = reinterpret_cast<uint4*>(Sh + (size_t)row * N);
    const int n8 = N >> 3;                       // 8 halves per uint4
    for (int i = threadIdx.x; i < n8; i += 256) {
        uint4 u = prow[i];
        uint32_t w[4] = {u.x, u.y, u.z, u.w};
#pragma unroll
        for (int j = 0; j < 4; j++) {
            __half2 h2 = *reinterpret_cast<__half2*>(&w[j]);
            float2 xy = __half22float2(h2);
            float a = xy.x * scale, b = xy.y * scale;
            a = 0.5f * a * (1.f + erff(a * inv_sqrt2));
            b = 0.5f * b * (1.f + erff(b * inv_sqrt2));
            __half2 r = __floats2half2_rn(a, b);
            w[j] = *reinterpret_cast<uint32_t*>(&r);
        }
        prow[i] = make_uint4(w[0], w[1], w[2], w[3]);
    }
}

__global__ __launch_bounds__(256) void transpose_h_kernel(
    const float* __restrict__ V, __half* __restrict__ VTh, int R, int Ccols)
{
    __shared__ float tbuf[32][33];
    int c0 = blockIdx.x * 32, r0 = blockIdx.y * 32;
    int x = threadIdx.x, y = threadIdx.y;
#pragma unroll
    for (int j = 0; j < 32; j += 8)
        tbuf[y + j][x] = V[(size_t)(r0 + y + j) * Ccols + c0 + x];
    __syncthreads();
    int k = x & 15;
    int px = (x & ~15) + 4 * ((k & 7) >> 1) + (k & 1) + 2 * (k >> 3);
#pragma unroll
    for (int j = 0; j < 32; j += 8)
        VTh[(size_t)(c0 + y + j) * R + r0 + px] = __float2half_rn(tbuf[x][y + j]);
}

__global__ __launch_bounds__(256) void sum4_kernel(
    const float4* __restrict__ p, float4* __restrict__ out, int n4, size_t stride4)
{
    int i = blockIdx.x * 256 + threadIdx.x;
    if (i >= n4) return;
    float4 a = p[i], b = p[i + stride4], c = p[i + 2 * stride4], d = p[i + 3 * stride4];
    out[i] = make_float4((a.x + b.x) + (c.x + d.x),
                         (a.y + b.y) + (c.y + d.y),
                         (a.z + b.z) + (c.z + d.z),
                         (a.w + b.w) + (c.w + d.w));
}

// ---------------------------------------------------------------------------
extern "C" void kernel_launch(void* const* d_in, const int* in_sizes, int n_in,
                              void* d_out, int out_size)
{
    const float* q = (const float*)d_in[0];
    const float* k = (const float*)d_in[1];
    const float* v = (const float*)d_in[2];
    float* out = (float*)d_out;

    float *P, *SQ;
    __half *Gh, *VTh, *QTh, *KTh;
    cudaGetSymbolAddress((void**)&Gh,  g_Gh);
    cudaGetSymbolAddress((void**)&VTh, g_VTh);
    cudaGetSymbolAddress((void**)&QTh, g_QTh);
    cudaGetSymbolAddress((void**)&KTh, g_KTh);
    cudaGetSymbolAddress((void**)&P,   g_P);
    cudaGetSymbolAddress((void**)&SQ,  g_SQ);

    static bool attr_done = false;
    if (!attr_done) {
        cudaFuncSetAttribute((const void*)gemm_fp16<true>,
                             cudaFuncAttributeMaxDynamicSharedMemorySize, SMEMH_BYTES);
        cudaFuncSetAttribute((const void*)gemm_fp16<false>,
                             cudaFuncAttributeMaxDynamicSharedMemorySize, SMEMH_BYTES);
        attr_done = true;
    }

    const int M = 8192, NBANK = 8192, D = 1024;
    const int ngroups = (M * D) / 16;
    const int KCHUNK = 2048;

    stage_h_kernel<<<(ngroups + 255) / 256, 256>>>((const float4*)q, QTh, ngroups);
    stage_h_kernel<<<(ngroups + 255) / 256, 256>>>((const float4*)k, KTh, ngroups);
    transpose_h_kernel<<<dim3(D / 32, NBANK / 32), dim3(32, 8)>>>(v, VTh, NBANK, D);

    // S = q @ k^T -> fp16, P2 cols, fused row-sumsq
    gemm_fp16<true><<<dim3(NBANK / BN, M / BM, 1), 256, SMEMH_BYTES>>>(
        QTh, KTh, Gh, SQ, M, NBANK, D, D, D);

    // G = gelu(scale*S) in place on fp16
    norm_gelu_inplace_kernel<<<M, 256>>>(Gh, SQ, NBANK);

    // out partials = G @ vT^T, split-K x4
    gemm_fp16<false><<<dim3(D / BN, M / BM, 4), 256, SMEMH_BYTES>>>(
        Gh, VTh, P, nullptr, M, D, KCHUNK, NBANK, NBANK);

    const int n4 = (M * D) / 4;
    sum4_kernel<<<(n4 + 255) / 256, 256>>>((const float4*)P, (float4*)out, n4,
                                           (size_t)M * D / 4);
}

// round 14
// speedup vs baseline: 1.1630x; 1.1630x over previous
#include <cuda_runtime.h>
#include <cuda_fp16.h>
#include <cstdint>

// ---------------------------------------------------------------------------
// S = q @ k^T  [8192,8192];  G = gelu_exact(S/||S||_row*sqrt(8192));
// out = G @ v  [8192,1024].
// fp16 m16n8k16 mma.sync, fp32 accum. SLDH=80 (pair-stride 20 ≡ 4 mod 16:
// verified conflict-free LDS.64 — SLDH=72 of R12 was a 2-way conflict bug).
// GEMM1 stores S directly as fp16 (P2 cols, half2 stores) + fused sumsq;
// norm+gelu in place on fp16; GEMM2 split-K x4 + sum4.
// ---------------------------------------------------------------------------

static __device__ __half g_Gh [8192ull * 8192ull];    // 128 MB S/G fp16 (P2 cols)
static __device__ __half g_VTh[1024ull * 8192ull];    // 16 MB  v^T fp16 (P2 k)
static __device__ __half g_QTh[8192ull * 1024ull];    // 16 MB  q fp16 (P2 k)
static __device__ __half g_KTh[8192ull * 1024ull];    // 16 MB  k fp16 (P2 k)
static __device__ float  g_P  [4ull * 8192ull * 1024ull]; // 128 MB split-K partials
static __device__ float  g_SQ [8192ull * 128ull];     // 4 MB sumsq partials

__device__ __forceinline__ void cp16(uint32_t dst_s, const void* src) {
    asm volatile("cp.async.cg.shared.global [%0], [%1], 16;\n" :: "r"(dst_s), "l"(src));
}

__device__ __forceinline__ uint2 lds64(uint32_t addr) {
    uint2 r;
    asm volatile("ld.shared.v2.b32 {%0, %1}, [%2];" : "=r"(r.x), "=r"(r.y) : "r"(addr));
    return r;
}

// =========================== unified fp16 GEMM =============================
constexpr int BM = 256, BN = 128;
constexpr int BKH  = 64;                 // halves per k-iter
constexpr int SLDH = 80;                 // pair-stride 20 ≡ 4 (mod 16): conflict-free
constexpr int STAGES = 3;
constexpr int TILEAH = BM * SLDH;        // 20480 halves
constexpr int TILEBH = BN * SLDH;        // 10240 halves
constexpr int STAGEH = TILEAH + TILEBH;  // 30720 halves
constexpr unsigned SMEMH_BYTES = STAGES * STAGEH * 2;  // 184320 B
constexpr int ROWB = 32 * SLDH * 2;      // 5120
constexpr int MTB  = 16 * SLDH * 2;      // 2560
constexpr int NTB  = 8 * SLDH * 2;       // 1280

__device__ __forceinline__ void mma_f16(float* d, uint2 a, uint2 a8, uint2 b) {
    asm volatile(
        "mma.sync.aligned.m16n8k16.row.col.f32.f16.f16.f32 "
        "{%0,%1,%2,%3}, {%4,%5,%6,%7}, {%8,%9}, {%0,%1,%2,%3};\n"
        : "+f"(d[0]), "+f"(d[1]), "+f"(d[2]), "+f"(d[3])
        : "r"(a.x), "r"(a8.x), "r"(a.y), "r"(a8.y), "r"(b.x), "r"(b.y));
}

struct FragH {
    uint2 a[4];
    uint2 a8[4];
    uint2 b[8];
};

// G1PHASE: epilogue stores fp16 (P2 cols) + fused sumsq. Else fp32 float2.
template <bool G1PHASE>
__global__ __launch_bounds__(256, 1) void gemm_fp16(
    const __half* __restrict__ A, const __half* __restrict__ B, void* __restrict__ Cv,
    float* __restrict__ sqpart,
    int M, int N, int kcount, int strideA, int strideB)
{
    extern __shared__ __half smh[];
    const uint32_t smem_s = (uint32_t)__cvta_generic_to_shared(smh);

    const int tid  = threadIdx.x;
    const int lane = tid & 31;
    const int wid  = tid >> 5;
    const int wm   = wid & 3;
    const int wn   = wid >> 2;
    const long bm = (long)blockIdx.y * BM;
    const long bn = (long)blockIdx.x * BN;
    const int kbase = blockIdx.z * kcount;

    float acc[4][8][4];
#pragma unroll
    for (int i = 0; i < 4; i++)
#pragma unroll
        for (int j = 0; j < 8; j++)
#pragma unroll
            for (int c = 0; c < 4; c++) acc[i][j][c] = 0.f;

    const int nk = kcount / BKH;

    // ---- staging ----
    const int rowA = tid >> 3;
    const int colh = (tid & 7) * 8;
    const __half* aG = A + (size_t)(bm + rowA) * strideA + kbase + colh;
    const __half* bG = B + (size_t)(bn + rowA) * strideB + kbase + colh;
    const uint32_t dA0 = (uint32_t)(rowA * SLDH + colh) * 2u;
    const uint32_t dB0 = (uint32_t)(TILEAH * 2) + dA0;

    auto load_stage = [&](int s, int kt) {
        const uint32_t sb = smem_s + (uint32_t)s * (STAGEH * 2);
        const __half* ak = aG + kt * BKH;
        const __half* bk = bG + kt * BKH;
#pragma unroll
        for (int i = 0; i < 8; i++)
            cp16(sb + dA0 + i * ROWB, ak + (size_t)i * 32 * strideA);
#pragma unroll
        for (int i = 0; i < 4; i++)
            cp16(sb + dB0 + i * ROWB, bk + (size_t)i * 32 * strideB);
        asm volatile("cp.async.commit_group;\n");
    };

#pragma unroll
    for (int s = 0; s < STAGES - 1; s++) load_stage(s, s);

    // ---- fragment base offsets ----
    const int t    = lane & 3;
    const int qrow = lane >> 2;
    const uint32_t aW0 = (uint32_t)((wm * 64 + qrow) * SLDH + 4 * t) * 2u;
    const uint32_t bW0 = (uint32_t)(TILEAH * 2) +
                         (uint32_t)((wn * 64 + qrow) * SLDH + 4 * t) * 2u;

    FragH f[2];

    auto load_frags = [&](uint32_t aW, uint32_t bW, FragH& F) {
#pragma unroll
        for (int mt = 0; mt < 4; mt++) {
            F.a[mt]  = lds64(aW + mt * MTB);
            F.a8[mt] = lds64(aW + mt * MTB + NTB);
        }
#pragma unroll
        for (int nt = 0; nt < 8; nt++)
            F.b[nt] = lds64(bW + nt * NTB);
    };

    auto mma_all = [&](const FragH& F) {
#pragma unroll
        for (int nt = 0; nt < 8; nt++)
#pragma unroll
            for (int mt = 0; mt < 4; mt++)
                mma_f16(acc[mt][nt], F.a[mt], F.a8[mt], F.b[nt]);
    };

    for (int kt = 0; kt < nk; kt++) {
        asm volatile("cp.async.wait_group %0;\n" :: "n"(STAGES - 2));
        __syncthreads();

        if (kt + STAGES - 1 < nk) {
            load_stage((kt + STAGES - 1) % STAGES, kt + STAGES - 1);
        } else {
            asm volatile("cp.async.commit_group;\n");
        }

        const uint32_t sb = smem_s + (uint32_t)(kt % STAGES) * (STAGEH * 2);
        const uint32_t aW = sb + aW0;
        const uint32_t bW = sb + bW0;

        load_frags(aW, bW, f[0]);
#pragma unroll
        for (int g = 0; g < 4; g++) {
            if (g < 3) load_frags(aW + (g + 1) * 32, bW + (g + 1) * 32, f[(g + 1) & 1]);
            mma_all(f[g & 1]);
        }
    }

    if (G1PHASE) {
        // fused per-row sumsq partials (fp32 accs, pre-rounding)
        const int pidx = blockIdx.x * 2 + wn;
#pragma unroll
        for (int mt = 0; mt < 4; mt++) {
            float s0 = 0.f, s1 = 0.f;
#pragma unroll
            for (int nt = 0; nt < 8; nt++) {
                s0 += acc[mt][nt][0] * acc[mt][nt][0] + acc[mt][nt][1] * acc[mt][nt][1];
                s1 += acc[mt][nt][2] * acc[mt][nt][2] + acc[mt][nt][3] * acc[mt][nt][3];
            }
            s0 += __shfl_xor_sync(0xffffffffu, s0, 1);
            s0 += __shfl_xor_sync(0xffffffffu, s0, 2);
            s1 += __shfl_xor_sync(0xffffffffu, s1, 1);
            s1 += __shfl_xor_sync(0xffffffffu, s1, 2);
            if (t == 0) {
                long r = bm + wm * 64 + mt * 16 + qrow;
                sqpart[(size_t)r * 128 + pidx]       = s0;
                sqpart[(size_t)(r + 8) * 128 + pidx] = s1;
            }
        }
        // fp16 epilogue, P2 layout: cols (2t,2t+1) of 8-group h=nt&1 ->
        // adjacent P2 slots 4t+2h, 4t+2h+1 -> one half2 store per pair.
        __half* Ch = (__half*)Cv;
#pragma unroll
        for (int mt = 0; mt < 4; mt++) {
            long r0 = bm + wm * 64 + mt * 16 + qrow;
#pragma unroll
            for (int nt = 0; nt < 8; nt++) {
                long c0 = bn + wn * 64 + (nt >> 1) * 16 + 4 * t + 2 * (nt & 1);
                *reinterpret_cast<__half2*>(&Ch[(size_t)r0 * N + c0]) =
                    __floats2half2_rn(acc[mt][nt][0], acc[mt][nt][1]);
                *reinterpret_cast<__half2*>(&Ch[(size_t)(r0 + 8) * N + c0]) =
                    __floats2half2_rn(acc[mt][nt][2], acc[mt][nt][3]);
            }
        }
    } else {
        float* C = (float*)Cv + (size_t)blockIdx.z * M * (size_t)N;
#pragma unroll
        for (int mt = 0; mt < 4; mt++) {
            long r0 = bm + wm * 64 + mt * 16 + qrow;
#pragma unroll
            for (int nt = 0; nt < 8; nt++) {
                long c0 = bn + wn * 64 + nt * 8 + 2 * t;
                *reinterpret_cast<float2*>(&C[(size_t)r0 * N + c0]) =
                    make_float2(acc[mt][nt][0], acc[mt][nt][1]);
                *reinterpret_cast<float2*>(&C[(size_t)(r0 + 8) * N + c0]) =
                    make_float2(acc[mt][nt][2], acc[mt][nt][3]);
            }
        }
    }
}

// ======================= staging / elementwise kernels =====================
__device__ __constant__ int c_invM[16] = {0,1,8,9,2,3,10,11,4,5,12,13,6,7,14,15};

__global__ __launch_bounds__(256) void stage_h_kernel(
    const float4* __restrict__ in, __half* __restrict__ out, int ngroups)
{
    int g = blockIdx.x * 256 + threadIdx.x;
    if (g >= ngroups) return;
    float x[16];
    float4 v0 = in[4 * g], v1 = in[4 * g + 1], v2 = in[4 * g + 2], v3 = in[4 * g + 3];
    x[0]=v0.x; x[1]=v0.y; x[2]=v0.z; x[3]=v0.w;
    x[4]=v1.x; x[5]=v1.y; x[6]=v1.z; x[7]=v1.w;
    x[8]=v2.x; x[9]=v2.y; x[10]=v2.z; x[11]=v2.w;
    x[12]=v3.x; x[13]=v3.y; x[14]=v3.z; x[15]=v3.w;
    uint32_t u[8];
#pragma unroll
    for (int j = 0; j < 8; j++) {
        __half2 h2 = __floats2half2_rn(x[c_invM[2 * j]], x[c_invM[2 * j + 1]]);
        u[j] = *reinterpret_cast<uint32_t*>(&h2);
    }
    uint4* dst = reinterpret_cast<uint4*>(out + (size_t)g * 16);
    dst[0] = make_uint4(u[0], u[1], u[2], u[3]);
    dst[1] = make_uint4(u[4], u[5], u[6], u[7]);
}

// IN-PLACE fp16 norm+gelu (P2 layout passes through).
__global__ __launch_bounds__(256) void norm_gelu_inplace_kernel(
    __half* __restrict__ Sh, const float* __restrict__ sqpart, int N)
{
    const int row = blockIdx.x;
    float ss = (threadIdx.x < 128) ? sqpart[(size_t)row * 128 + threadIdx.x] : 0.f;
    __shared__ float red[8];
#pragma unroll
    for (int o = 16; o > 0; o >>= 1) ss += __shfl_xor_sync(0xffffffffu, ss, o);
    if ((threadIdx.x & 31) == 0) red[threadIdx.x >> 5] = ss;
    __syncthreads();
    if (threadIdx.x < 32) {
        float v = (threadIdx.x < 8) ? red[threadIdx.x] : 0.f;
#pragma unroll
        for (int o = 4; o > 0; o >>= 1) v += __shfl_xor_sync(0xffffffffu, v, o);
        if (threadIdx.x == 0) red[0] = v;
    }
    __syncthreads();
    const float scale = sqrtf((float)N / red[0]);
    const float inv_sqrt2 = 0.70710678118654752440f;

    uint4* prow = reinterpret_cast<uint4*>(Sh + (size_t)row * N);
    const int n8 = N >> 3;
    for (int i = threadIdx.x; i < n8; i += 256) {
        uint4 u = prow[i];
        uint32_t w[4] = {u.x, u.y, u.z, u.w};
#pragma unroll
        for (int j = 0; j < 4; j++) {
            __half2 h2 = *reinterpret_cast<__half2*>(&w[j]);
            float2 xy = __half22float2(h2);
            float a = xy.x * scale, b = xy.y * scale;
            a = 0.5f * a * (1.f + erff(a * inv_sqrt2));
            b = 0.5f * b * (1.f + erff(b * inv_sqrt2));
            __half2 r = __floats2half2_rn(a, b);
            w[j] = *reinterpret_cast<uint32_t*>(&r);
        }
        prow[i] = make_uint4(w[0], w[1], w[2], w[3]);
    }
}

__global__ __launch_bounds__(256) void transpose_h_kernel(
    const float* __restrict__ V, __half* __restrict__ VTh, int R, int Ccols)
{
    __shared__ float tbuf[32][33];
    int c0 = blockIdx.x * 32, r0 = blockIdx.y * 32;
    int x = threadIdx.x, y = threadIdx.y;
#pragma unroll
    for (int j = 0; j < 32; j += 8)
        tbuf[y + j][x] = V[(size_t)(r0 + y + j) * Ccols + c0 + x];
    __syncthreads();
    int k = x & 15;
    int px = (x & ~15) + 4 * ((k & 7) >> 1) + (k & 1) + 2 * (k >> 3);
#pragma unroll
    for (int j = 0; j < 32; j += 8)
        VTh[(size_t)(c0 + y + j) * R + r0 + px] = __float2half_rn(tbuf[x][y + j]);
}

__global__ __launch_bounds__(256) void sum4_kernel(
    const float4* __restrict__ p, float4* __restrict__ out, int n4, size_t stride4)
{
    int i = blockIdx.x * 256 + threadIdx.x;
    if (i >= n4) return;
    float4 a = p[i], b = p[i + stride4], c = p[i + 2 * stride4], d = p[i + 3 * stride4];
    out[i] = make_float4((a.x + b.x) + (c.x + d.x),
                         (a.y + b.y) + (c.y + d.y),
                         (a.z + b.z) + (c.z + d.z),
                         (a.w + b.w) + (c.w + d.w));
}

// ---------------------------------------------------------------------------
extern "C" void kernel_launch(void* const* d_in, const int* in_sizes, int n_in,
                              void* d_out, int out_size)
{
    const float* q = (const float*)d_in[0];
    const float* k = (const float*)d_in[1];
    const float* v = (const float*)d_in[2];
    float* out = (float*)d_out;

    float *P, *SQ;
    __half *Gh, *VTh, *QTh, *KTh;
    cudaGetSymbolAddress((void**)&Gh,  g_Gh);
    cudaGetSymbolAddress((void**)&VTh, g_VTh);
    cudaGetSymbolAddress((void**)&QTh, g_QTh);
    cudaGetSymbolAddress((void**)&KTh, g_KTh);
    cudaGetSymbolAddress((void**)&P,   g_P);
    cudaGetSymbolAddress((void**)&SQ,  g_SQ);

    static bool attr_done = false;
    if (!attr_done) {
        cudaFuncSetAttribute((const void*)gemm_fp16<true>,
                             cudaFuncAttributeMaxDynamicSharedMemorySize, SMEMH_BYTES);
        cudaFuncSetAttribute((const void*)gemm_fp16<false>,
                             cudaFuncAttributeMaxDynamicSharedMemorySize, SMEMH_BYTES);
        attr_done = true;
    }

    const int M = 8192, NBANK = 8192, D = 1024;
    const int ngroups = (M * D) / 16;
    const int KCHUNK = 2048;

    stage_h_kernel<<<(ngroups + 255) / 256, 256>>>((const float4*)q, QTh, ngroups);
    stage_h_kernel<<<(ngroups + 255) / 256, 256>>>((const float4*)k, KTh, ngroups);
    transpose_h_kernel<<<dim3(D / 32, NBANK / 32), dim3(32, 8)>>>(v, VTh, NBANK, D);

    // S = q @ k^T -> fp16, P2 cols, fused row-sumsq
    gemm_fp16<true><<<dim3(NBANK / BN, M / BM, 1), 256, SMEMH_BYTES>>>(
        QTh, KTh, Gh, SQ, M, NBANK, D, D, D);

    // G = gelu(scale*S) in place on fp16
    norm_gelu_inplace_kernel<<<M, 256>>>(Gh, SQ, NBANK);

    // out partials = G @ vT^T, split-K x4
    gemm_fp16<false><<<dim3(D / BN, M / BM, 4), 256, SMEMH_BYTES>>>(
        Gh, VTh, P, nullptr, M, D, KCHUNK, NBANK, NBANK);

    const int n4 = (M * D) / 4;
    sum4_kernel<<<(n4 + 255) / 256, 256>>>((const float4*)P, (float4*)out, n4,
                                           (size_t)M * D / 4);
}

// round 15
// speedup vs baseline: 1.1958x; 1.0282x over previous
#include <cuda_runtime.h>
#include <cuda_fp16.h>
#include <cstdint>

// ---------------------------------------------------------------------------
// S = q @ k^T  [8192,8192];  G = gelu_exact(S/||S||_row*sqrt(8192));
// out = G @ v  [8192,1024].
// fp16 m16n8k16 mma.sync, fp32 accum — measured saturated at ~303 TF/s
// (legacy HMMA fp32-acc rate wall). SLDH=80 conflict-free layout.
// GEMM1 -> fp16 S (P2 cols) + fused sumsq; in-place fp16 norm+gelu;
// GEMM2 split-K x4 with fp16 partials; v-transpose overlapped on a side
// stream; q/k staging merged into one launch.
// ---------------------------------------------------------------------------

static __device__ __half g_Gh [8192ull * 8192ull];    // 128 MB S/G fp16 (P2 cols)
static __device__ __half g_VTh[1024ull * 8192ull];    // 16 MB  v^T fp16 (P2 k)
static __device__ __half g_QTh[8192ull * 1024ull];    // 16 MB  q fp16 (P2 k)
static __device__ __half g_KTh[8192ull * 1024ull];    // 16 MB  k fp16 (P2 k)
static __device__ __half g_P  [4ull * 8192ull * 1024ull]; // 64 MB split-K fp16 partials
static __device__ float  g_SQ [8192ull * 128ull];     // 4 MB sumsq partials

__device__ __forceinline__ void cp16(uint32_t dst_s, const void* src) {
    asm volatile("cp.async.cg.shared.global [%0], [%1], 16;\n" :: "r"(dst_s), "l"(src));
}

__device__ __forceinline__ uint2 lds64(uint32_t addr) {
    uint2 r;
    asm volatile("ld.shared.v2.b32 {%0, %1}, [%2];" : "=r"(r.x), "=r"(r.y) : "r"(addr));
    return r;
}

// =========================== unified fp16 GEMM =============================
constexpr int BM = 256, BN = 128;
constexpr int BKH  = 64;                 // halves per k-iter
constexpr int SLDH = 80;                 // pair-stride 20 ≡ 4 (mod 16): conflict-free
constexpr int STAGES = 3;
constexpr int TILEAH = BM * SLDH;
constexpr int TILEBH = BN * SLDH;
constexpr int STAGEH = TILEAH + TILEBH;
constexpr unsigned SMEMH_BYTES = STAGES * STAGEH * 2;  // 184320 B
constexpr int ROWB = 32 * SLDH * 2;
constexpr int MTB  = 16 * SLDH * 2;
constexpr int NTB  = 8 * SLDH * 2;

__device__ __forceinline__ void mma_f16(float* d, uint2 a, uint2 a8, uint2 b) {
    asm volatile(
        "mma.sync.aligned.m16n8k16.row.col.f32.f16.f16.f32 "
        "{%0,%1,%2,%3}, {%4,%5,%6,%7}, {%8,%9}, {%0,%1,%2,%3};\n"
        : "+f"(d[0]), "+f"(d[1]), "+f"(d[2]), "+f"(d[3])
        : "r"(a.x), "r"(a8.x), "r"(a.y), "r"(a8.y), "r"(b.x), "r"(b.y));
}

struct FragH {
    uint2 a[4];
    uint2 a8[4];
    uint2 b[8];
};

// G1PHASE: fp16 epilogue in P2 layout + fused sumsq. Else fp16 split-K partials.
template <bool G1PHASE>
__global__ __launch_bounds__(256, 1) void gemm_fp16(
    const __half* __restrict__ A, const __half* __restrict__ B, __half* __restrict__ Ch,
    float* __restrict__ sqpart,
    int M, int N, int kcount, int strideA, int strideB)
{
    extern __shared__ __half smh[];
    const uint32_t smem_s = (uint32_t)__cvta_generic_to_shared(smh);

    const int tid  = threadIdx.x;
    const int lane = tid & 31;
    const int wid  = tid >> 5;
    const int wm   = wid & 3;
    const int wn   = wid >> 2;
    const long bm = (long)blockIdx.y * BM;
    const long bn = (long)blockIdx.x * BN;
    const int kbase = blockIdx.z * kcount;
    if (!G1PHASE) Ch += (size_t)blockIdx.z * M * (size_t)N;

    float acc[4][8][4];
#pragma unroll
    for (int i = 0; i < 4; i++)
#pragma unroll
        for (int j = 0; j < 8; j++)
#pragma unroll
            for (int c = 0; c < 4; c++) acc[i][j][c] = 0.f;

    const int nk = kcount / BKH;

    // ---- staging ----
    const int rowA = tid >> 3;
    const int colh = (tid & 7) * 8;
    const __half* aG = A + (size_t)(bm + rowA) * strideA + kbase + colh;
    const __half* bG = B + (size_t)(bn + rowA) * strideB + kbase + colh;
    const uint32_t dA0 = (uint32_t)(rowA * SLDH + colh) * 2u;
    const uint32_t dB0 = (uint32_t)(TILEAH * 2) + dA0;

    auto load_stage = [&](int s, int kt) {
        const uint32_t sb = smem_s + (uint32_t)s * (STAGEH * 2);
        const __half* ak = aG + kt * BKH;
        const __half* bk = bG + kt * BKH;
#pragma unroll
        for (int i = 0; i < 8; i++)
            cp16(sb + dA0 + i * ROWB, ak + (size_t)i * 32 * strideA);
#pragma unroll
        for (int i = 0; i < 4; i++)
            cp16(sb + dB0 + i * ROWB, bk + (size_t)i * 32 * strideB);
        asm volatile("cp.async.commit_group;\n");
    };

#pragma unroll
    for (int s = 0; s < STAGES - 1; s++) load_stage(s, s);

    // ---- fragment base offsets ----
    const int t    = lane & 3;
    const int qrow = lane >> 2;
    const uint32_t aW0 = (uint32_t)((wm * 64 + qrow) * SLDH + 4 * t) * 2u;
    const uint32_t bW0 = (uint32_t)(TILEAH * 2) +
                         (uint32_t)((wn * 64 + qrow) * SLDH + 4 * t) * 2u;

    FragH f[2];

    auto load_frags = [&](uint32_t aW, uint32_t bW, FragH& F) {
#pragma unroll
        for (int mt = 0; mt < 4; mt++) {
            F.a[mt]  = lds64(aW + mt * MTB);
            F.a8[mt] = lds64(aW + mt * MTB + NTB);
        }
#pragma unroll
        for (int nt = 0; nt < 8; nt++)
            F.b[nt] = lds64(bW + nt * NTB);
    };

    auto mma_all = [&](const FragH& F) {
#pragma unroll
        for (int nt = 0; nt < 8; nt++)
#pragma unroll
            for (int mt = 0; mt < 4; mt++)
                mma_f16(acc[mt][nt], F.a[mt], F.a8[mt], F.b[nt]);
    };

    for (int kt = 0; kt < nk; kt++) {
        asm volatile("cp.async.wait_group %0;\n" :: "n"(STAGES - 2));
        __syncthreads();

        if (kt + STAGES - 1 < nk) {
            load_stage((kt + STAGES - 1) % STAGES, kt + STAGES - 1);
        } else {
            asm volatile("cp.async.commit_group;\n");
        }

        const uint32_t sb = smem_s + (uint32_t)(kt % STAGES) * (STAGEH * 2);
        const uint32_t aW = sb + aW0;
        const uint32_t bW = sb + bW0;

        load_frags(aW, bW, f[0]);
#pragma unroll
        for (int g = 0; g < 4; g++) {
            if (g < 3) load_frags(aW + (g + 1) * 32, bW + (g + 1) * 32, f[(g + 1) & 1]);
            mma_all(f[g & 1]);
        }
    }

    if (G1PHASE) {
        // fused per-row sumsq partials (fp32 accs, pre-rounding)
        const int pidx = blockIdx.x * 2 + wn;
#pragma unroll
        for (int mt = 0; mt < 4; mt++) {
            float s0 = 0.f, s1 = 0.f;
#pragma unroll
            for (int nt = 0; nt < 8; nt++) {
                s0 += acc[mt][nt][0] * acc[mt][nt][0] + acc[mt][nt][1] * acc[mt][nt][1];
                s1 += acc[mt][nt][2] * acc[mt][nt][2] + acc[mt][nt][3] * acc[mt][nt][3];
            }
            s0 += __shfl_xor_sync(0xffffffffu, s0, 1);
            s0 += __shfl_xor_sync(0xffffffffu, s0, 2);
            s1 += __shfl_xor_sync(0xffffffffu, s1, 1);
            s1 += __shfl_xor_sync(0xffffffffu, s1, 2);
            if (t == 0) {
                long r = bm + wm * 64 + mt * 16 + qrow;
                sqpart[(size_t)r * 128 + pidx]       = s0;
                sqpart[(size_t)(r + 8) * 128 + pidx] = s1;
            }
        }
        // fp16 epilogue, P2 layout: cols (2t,2t+1) of 8-group h=nt&1 ->
        // adjacent P2 slots 4t+2h, 4t+2h+1 -> one half2 store per pair.
#pragma unroll
        for (int mt = 0; mt < 4; mt++) {
            long r0 = bm + wm * 64 + mt * 16 + qrow;
#pragma unroll
            for (int nt = 0; nt < 8; nt++) {
                long c0 = bn + wn * 64 + (nt >> 1) * 16 + 4 * t + 2 * (nt & 1);
                *reinterpret_cast<__half2*>(&Ch[(size_t)r0 * N + c0]) =
                    __floats2half2_rn(acc[mt][nt][0], acc[mt][nt][1]);
                *reinterpret_cast<__half2*>(&Ch[(size_t)(r0 + 8) * N + c0]) =
                    __floats2half2_rn(acc[mt][nt][2], acc[mt][nt][3]);
            }
        }
    } else {
        // fp16 split-K partials, natural layout, half2 stores
#pragma unroll
        for (int mt = 0; mt < 4; mt++) {
            long r0 = bm + wm * 64 + mt * 16 + qrow;
#pragma unroll
            for (int nt = 0; nt < 8; nt++) {
                long c0 = bn + wn * 64 + nt * 8 + 2 * t;
                *reinterpret_cast<__half2*>(&Ch[(size_t)r0 * N + c0]) =
                    __floats2half2_rn(acc[mt][nt][0], acc[mt][nt][1]);
                *reinterpret_cast<__half2*>(&Ch[(size_t)(r0 + 8) * N + c0]) =
                    __floats2half2_rn(acc[mt][nt][2], acc[mt][nt][3]);
            }
        }
    }
}

// ======================= staging / elementwise kernels =====================
__device__ __constant__ int c_invM[16] = {0,1,8,9,2,3,10,11,4,5,12,13,6,7,14,15};

// fp32 (natural k) -> fp16 (P2 k), q and k in one launch (blockIdx.y picks).
__global__ __launch_bounds__(256) void stage_h2_kernel(
    const float4* __restrict__ q, __half* __restrict__ qo,
    const float4* __restrict__ k, __half* __restrict__ ko, int ngroups)
{
    const float4* in  = blockIdx.y ? k  : q;
    __half*       out = blockIdx.y ? ko : qo;
    int g = blockIdx.x * 256 + threadIdx.x;
    if (g >= ngroups) return;
    float x[16];
    float4 v0 = in[4 * g], v1 = in[4 * g + 1], v2 = in[4 * g + 2], v3 = in[4 * g + 3];
    x[0]=v0.x; x[1]=v0.y; x[2]=v0.z; x[3]=v0.w;
    x[4]=v1.x; x[5]=v1.y; x[6]=v1.z; x[7]=v1.w;
    x[8]=v2.x; x[9]=v2.y; x[10]=v2.z; x[11]=v2.w;
    x[12]=v3.x; x[13]=v3.y; x[14]=v3.z; x[15]=v3.w;
    uint32_t u[8];
#pragma unroll
    for (int j = 0; j < 8; j++) {
        __half2 h2 = __floats2half2_rn(x[c_invM[2 * j]], x[c_invM[2 * j + 1]]);
        u[j] = *reinterpret_cast<uint32_t*>(&h2);
    }
    uint4* dst = reinterpret_cast<uint4*>(out + (size_t)g * 16);
    dst[0] = make_uint4(u[0], u[1], u[2], u[3]);
    dst[1] = make_uint4(u[4], u[5], u[6], u[7]);
}

// IN-PLACE fp16 norm+gelu (P2 layout passes through).
__global__ __launch_bounds__(256) void norm_gelu_inplace_kernel(
    __half* __restrict__ Sh, const float* __restrict__ sqpart, int N)
{
    const int row = blockIdx.x;
    float ss = (threadIdx.x < 128) ? sqpart[(size_t)row * 128 + threadIdx.x] : 0.f;
    __shared__ float red[8];
#pragma unroll
    for (int o = 16; o > 0; o >>= 1) ss += __shfl_xor_sync(0xffffffffu, ss, o);
    if ((threadIdx.x & 31) == 0) red[threadIdx.x >> 5] = ss;
    __syncthreads();
    if (threadIdx.x < 32) {
        float v = (threadIdx.x < 8) ? red[threadIdx.x] : 0.f;
#pragma unroll
        for (int o = 4; o > 0; o >>= 1) v += __shfl_xor_sync(0xffffffffu, v, o);
        if (threadIdx.x == 0) red[0] = v;
    }
    __syncthreads();
    const float scale = sqrtf((float)N / red[0]);
    const float inv_sqrt2 = 0.70710678118654752440f;

    uint4* prow = reinterpret_cast<uint4*>(Sh + (size_t)row * N);
    const int n8 = N >> 3;
    for (int i = threadIdx.x; i < n8; i += 256) {
        uint4 u = prow[i];
        uint32_t w[4] = {u.x, u.y, u.z, u.w};
#pragma unroll
        for (int j = 0; j < 4; j++) {
            __half2 h2 = *reinterpret_cast<__half2*>(&w[j]);
            float2 xy = __half22float2(h2);
            float a = xy.x * scale, b = xy.y * scale;
            a = 0.5f * a * (1.f + erff(a * inv_sqrt2));
            b = 0.5f * b * (1.f + erff(b * inv_sqrt2));
            __half2 r = __floats2half2_rn(a, b);
            w[j] = *reinterpret_cast<uint32_t*>(&r);
        }
        prow[i] = make_uint4(w[0], w[1], w[2], w[3]);
    }
}

__global__ __launch_bounds__(256) void transpose_h_kernel(
    const float* __restrict__ V, __half* __restrict__ VTh, int R, int Ccols)
{
    __shared__ float tbuf[32][33];
    int c0 = blockIdx.x * 32, r0 = blockIdx.y * 32;
    int x = threadIdx.x, y = threadIdx.y;
#pragma unroll
    for (int j = 0; j < 32; j += 8)
        tbuf[y + j][x] = V[(size_t)(r0 + y + j) * Ccols + c0 + x];
    __syncthreads();
    int k = x & 15;
    int px = (x & ~15) + 4 * ((k & 7) >> 1) + (k & 1) + 2 * (k >> 3);
#pragma unroll
    for (int j = 0; j < 32; j += 8)
        VTh[(size_t)(c0 + y + j) * R + r0 + px] = __float2half_rn(tbuf[x][y + j]);
}

// Sum 4 fp16 split-K partials -> fp32 out. 8 halves per thread per buffer.
__global__ __launch_bounds__(256) void sum4_h_kernel(
    const uint4* __restrict__ p, float4* __restrict__ out, int n8, size_t stride8)
{
    int i = blockIdx.x * 256 + threadIdx.x;
    if (i >= n8) return;
    float r[8];
#pragma unroll
    for (int j = 0; j < 8; j++) r[j] = 0.f;
#pragma unroll
    for (int z = 0; z < 4; z++) {
        uint4 u = p[i + z * stride8];
        uint32_t w[4] = {u.x, u.y, u.z, u.w};
#pragma unroll
        for (int j = 0; j < 4; j++) {
            float2 xy = __half22float2(*reinterpret_cast<__half2*>(&w[j]));
            r[2 * j]     += xy.x;
            r[2 * j + 1] += xy.y;
        }
    }
    out[2 * i]     = make_float4(r[0], r[1], r[2], r[3]);
    out[2 * i + 1] = make_float4(r[4], r[5], r[6], r[7]);
}

// ---------------------------------------------------------------------------
extern "C" void kernel_launch(void* const* d_in, const int* in_sizes, int n_in,
                              void* d_out, int out_size)
{
    const float* q = (const float*)d_in[0];
    const float* k = (const float*)d_in[1];
    const float* v = (const float*)d_in[2];
    float* out = (float*)d_out;

    float *SQ;
    __half *Gh, *VTh, *QTh, *KTh, *P;
    cudaGetSymbolAddress((void**)&Gh,  g_Gh);
    cudaGetSymbolAddress((void**)&VTh, g_VTh);
    cudaGetSymbolAddress((void**)&QTh, g_QTh);
    cudaGetSymbolAddress((void**)&KTh, g_KTh);
    cudaGetSymbolAddress((void**)&P,   g_P);
    cudaGetSymbolAddress((void**)&SQ,  g_SQ);

    static cudaStream_t s2 = nullptr;
    static cudaEvent_t evFork = nullptr, evJoin = nullptr;
    static bool init_done = false;
    if (!init_done) {
        cudaFuncSetAttribute((const void*)gemm_fp16<true>,
                             cudaFuncAttributeMaxDynamicSharedMemorySize, SMEMH_BYTES);
        cudaFuncSetAttribute((const void*)gemm_fp16<false>,
                             cudaFuncAttributeMaxDynamicSharedMemorySize, SMEMH_BYTES);
        cudaStreamCreateWithFlags(&s2, cudaStreamNonBlocking);
        cudaEventCreateWithFlags(&evFork, cudaEventDisableTiming);
        cudaEventCreateWithFlags(&evJoin, cudaEventDisableTiming);
        init_done = true;
    }

    const int M = 8192, NBANK = 8192, D = 1024;
    const int ngroups = (M * D) / 16;
    const int KCHUNK = 2048;

    // fork: v-transpose on side stream, overlapped with staging + GEMM1
    cudaEventRecord(evFork, 0);
    cudaStreamWaitEvent(s2, evFork, 0);
    transpose_h_kernel<<<dim3(D / 32, NBANK / 32), dim3(32, 8), 0, s2>>>(v, VTh, NBANK, D);
    cudaEventRecord(evJoin, s2);

    // q + k staging, one launch
    stage_h2_kernel<<<dim3((ngroups + 255) / 256, 2), 256>>>(
        (const float4*)q, QTh, (const float4*)k, KTh, ngroups);

    // S = q @ k^T -> fp16, P2 cols, fused row-sumsq
    gemm_fp16<true><<<dim3(NBANK / BN, M / BM, 1), 256, SMEMH_BYTES>>>(
        QTh, KTh, Gh, SQ, M, NBANK, D, D, D);

    // G = gelu(scale*S) in place on fp16
    norm_gelu_inplace_kernel<<<M, 256>>>(Gh, SQ, NBANK);

    // join: VT must be ready before GEMM2
    cudaStreamWaitEvent(0, evJoin, 0);

    // out partials (fp16) = G @ vT^T, split-K x4
    gemm_fp16<false><<<dim3(D / BN, M / BM, 4), 256, SMEMH_BYTES>>>(
        Gh, VTh, P, nullptr, M, D, KCHUNK, NBANK, NBANK);

    // out = fp32 sum of 4 fp16 partials
    const int n8 = (M * D) / 8;
    sum4_h_kernel<<<(n8 + 255) / 256, 256>>>((const uint4*)P, (float4*)out, n8,
                                             (size_t)M * D / 8);
}